// round 5
// baseline (speedup 1.0000x reference)
#include <cuda_runtime.h>
#include <cstdint>

#define N_ROWS 16384
#define K_CODES 4096
#define D_DIM 512

#define TILE_M 128
#define TILE_N 128
#define NTILES 32

#define A_OFF 0
#define A_BYTES 65536             // 128 rows x 512 B
#define B_OFF 65536
#define B_STAGE 65536
#define CN_OFF (65536 * 3)
#define DYN_BYTES (CN_OFF + K_CODES * 4)   // 212992

#define MARGIN 2.5e-3f
#define MAX_CAND 32

#define SZQ (127.0f / 6.0f)                 // z quant scale
#define SCQ (127.0f * 4096.0f)              // codebook quant scale
// reconstruct: dist_approx = cn - 2*(SZ*SC)*idot, MS = -2*SZ*SC
#define MS  (-2.0f * (6.0f / 127.0f) / (127.0f * 4096.0f))

// -------- scratch (static device globals; no allocation) --------
__device__ int      g_zq[N_ROWS * 128];     // z int8 packed, 8 MB
__device__ int      g_cq[K_CODES * 128];    // codebook int8 packed, 2 MB
__device__ float    g_znorm[N_ROWS];
__device__ float    g_cnorm[K_CODES];
__device__ int      g_idx[N_ROWS];
__device__ float    g_partial[N_ROWS];
__device__ int      g_cand[N_ROWS * MAX_CAND];
__device__ unsigned g_cnt[N_ROWS];

// -------- helpers --------
__device__ __forceinline__ unsigned smem_u32(const void* p){
    unsigned a;
    asm("{ .reg .u64 t; cvta.to.shared.u64 t, %1; cvt.u32.u64 %0, t; }" : "=r"(a) : "l"(p));
    return a;
}
__device__ __forceinline__ void cp16(unsigned s, const void* g){
    asm volatile("cp.async.cg.shared.global [%0], [%1], 16;" :: "r"(s), "l"(g) : "memory");
}
__device__ __forceinline__ void dp4(int& acc, unsigned a, unsigned b){
    asm("dp4a.s32.s32 %0, %1, %2, %0;" : "+r"(acc) : "r"(a), "r"(b));
}
__device__ __forceinline__ unsigned enc_f(float f){
    unsigned b = __float_as_uint(f);
    return (b & 0x80000000u) ? ~b : (b | 0x80000000u);
}
__device__ __forceinline__ float dec_f(unsigned e){
    return (e & 0x80000000u) ? __uint_as_float(e ^ 0x80000000u) : __uint_as_float(~e);
}
__device__ __forceinline__ int q8(float v, float s){
    float t = fminf(fmaxf(v * s, -127.0f), 127.0f);
    return __float2int_rn(t);
}
__device__ __forceinline__ int pack4(int a, int b, int c, int d){
    return (a & 255) | ((b & 255) << 8) | ((c & 255) << 16) | ((d & 255) << 24);
}

// -------- prep_z: exact fp64 row norm (R1 order) + int8 quant + cnt init ----
__global__ void prep_z_kernel(const float* __restrict__ z){
    int w = (blockIdx.x * blockDim.x + threadIdx.x) >> 5;
    int lane = threadIdx.x & 31;
    if (w >= N_ROWS) return;
    const float* r = z + (size_t)w * D_DIM;
    double acc = 0.0;
    #pragma unroll 4
    for (int j = lane; j < D_DIM; j += 32){ float v = r[j]; acc += (double)v * (double)v; }
    #pragma unroll
    for (int o = 16; o > 0; o >>= 1) acc += __shfl_down_sync(0xffffffffu, acc, o);
    if (lane == 0){ g_znorm[w] = (float)acc; g_cnt[w] = 0u; }
    // quantize: lane handles words lane, lane+32, lane+64, lane+96
    const float4* r4 = (const float4*)r;
    #pragma unroll
    for (int jj = 0; jj < 4; jj++){
        int widx = lane + jj * 32;
        float4 v = r4[widx];
        g_zq[w * 128 + widx] = pack4(q8(v.x, SZQ), q8(v.y, SZQ), q8(v.z, SZQ), q8(v.w, SZQ));
    }
}

// -------- quantc: codebook int8 quant --------
__global__ void quantc_kernel(const float* __restrict__ cb){
    int i = blockIdx.x * blockDim.x + threadIdx.x;
    if (i < K_CODES * 128){
        float4 v = ((const float4*)cb)[i];
        g_cq[i] = pack4(q8(v.x, SCQ), q8(v.y, SCQ), q8(v.z, SCQ), q8(v.w, SCQ));
    }
}

// -------- cnorm (R1 order, exact) --------
__global__ void cnorm_kernel(const float* __restrict__ cb){
    int w = (blockIdx.x * blockDim.x + threadIdx.x) >> 5;
    int lane = threadIdx.x & 31;
    if (w >= K_CODES) return;
    const float* r = cb + (size_t)w * D_DIM;
    double acc = 0.0;
    #pragma unroll 4
    for (int j = lane; j < D_DIM; j += 32){ float v = r[j]; acc += (double)v * (double)v; }
    #pragma unroll
    for (int o = 16; o > 0; o >>= 1) acc += __shfl_down_sync(0xffffffffu, acc, o);
    if (lane == 0) g_cnorm[w] = (float)acc;
}

// -------- tile loaders (XOR-swizzled 16B chunks) --------
__device__ __forceinline__ void load_A(unsigned smA, int rowbase, int tid){
    const char* src = (const char*)g_zq;
    #pragma unroll
    for (int i = 0; i < 16; i++){
        int f = tid + i * 256;
        int r = f >> 5, c = f & 31;
        unsigned dst = smA + (unsigned)(r * 512 + ((c ^ ((r >> 2) & 7)) << 4));
        cp16(dst, src + (size_t)(rowbase + r) * 512 + (c << 4));
    }
}
__device__ __forceinline__ void load_B(unsigned smB, int nt, int tid){
    const char* src = (const char*)g_cq;
    #pragma unroll
    for (int i = 0; i < 16; i++){
        int f = tid + i * 256;
        int r = f >> 5, c = f & 31;
        unsigned dst = smB + (unsigned)(r * 512 + ((c ^ ((r >> 2) & 7)) << 4));
        cp16(dst, src + (size_t)(nt * TILE_N + r) * 512 + (c << 4));
    }
}

// -------- main int8 dp4a kernel: distances + candidate screening --------
extern __shared__ char sm_dyn[];
__global__ __launch_bounds__(256, 1)
void vq_dp4a_kernel()
{
    __shared__ unsigned s_tile[TILE_M];
    __shared__ float    s_run[TILE_M];

    const int tid = threadIdx.x;
    const int tx = tid & 15, ty = tid >> 4;
    const int rowbase = blockIdx.x * TILE_M;
    const unsigned smA = smem_u32(sm_dyn);
    float* cn_sm = (float*)(sm_dyn + CN_OFF);

    // prologue: A tile + B tile 0 (one cp.async group), cnorms, state init
    load_A(smA, rowbase, tid);
    load_B(smA + B_OFF, 0, tid);
    asm volatile("cp.async.commit_group;" ::: "memory");
    for (int i = tid; i < K_CODES; i += 256) cn_sm[i] = g_cnorm[i];
    if (tid < TILE_M){ s_tile[tid] = 0xFFFFFFFFu; s_run[tid] = 3.4e38f; }

    int acc[8][8];
    #pragma unroll
    for (int r = 0; r < 8; r++)
        #pragma unroll
        for (int c = 0; c < 8; c++) acc[r][c] = 0;

    // precompute per-thread row/code locals
    int arow[8], brow[8];
    #pragma unroll
    for (int j = 0; j < 8; j++){
        arow[j] = (j < 4) ? (ty * 4 + j) : (64 + ty * 4 + j - 4);
        brow[j] = (j < 4) ? (tx * 4 + j) : (64 + tx * 4 + j - 4);
    }

    for (int nt = 0; nt < NTILES; nt++){
        if (nt + 1 < NTILES){
            load_B(smA + B_OFF + (unsigned)(((nt + 1) & 1) * B_STAGE), nt + 1, tid);
            asm volatile("cp.async.commit_group;" ::: "memory");
            asm volatile("cp.async.wait_group 1;" ::: "memory");
        } else {
            asm volatile("cp.async.wait_group 0;" ::: "memory");
        }
        __syncthreads();

        const char* Bb = sm_dyn + B_OFF + (nt & 1) * B_STAGE;

        #pragma unroll 1
        for (int kc = 0; kc < 32; kc++){
            uint4 a[8], b[8];
            #pragma unroll
            for (int j = 0; j < 8; j++){
                a[j] = *(const uint4*)(sm_dyn + arow[j] * 512 + ((kc ^ ((arow[j] >> 2) & 7)) << 4));
                b[j] = *(const uint4*)(Bb + brow[j] * 512 + ((kc ^ ((brow[j] >> 2) & 7)) << 4));
            }
            #pragma unroll
            for (int r = 0; r < 8; r++)
                #pragma unroll
                for (int c = 0; c < 8; c++){
                    dp4(acc[r][c], a[r].x, b[c].x);
                    dp4(acc[r][c], a[r].y, b[c].y);
                    dp4(acc[r][c], a[r].z, b[c].z);
                    dp4(acc[r][c], a[r].w, b[c].w);
                }
        }

        // ---- epilogue for tile nt ----
        float vmin[8];
        #pragma unroll
        for (int r = 0; r < 8; r++) vmin[r] = 3.4e38f;
        #pragma unroll
        for (int r = 0; r < 8; r++)
            #pragma unroll
            for (int c = 0; c < 8; c++){
                float fv = fmaf(MS, (float)acc[r][c], cn_sm[nt * TILE_N + brow[c]]);
                acc[r][c] = __float_as_int(fv);
                vmin[r] = fminf(vmin[r], fv);
            }
        #pragma unroll
        for (int r = 0; r < 8; r++)
            atomicMin(&s_tile[arow[r]], enc_f(vmin[r]));
        __syncthreads();
        if (tid < TILE_M){
            s_run[tid] = fminf(s_run[tid], dec_f(s_tile[tid]));
            s_tile[tid] = 0xFFFFFFFFu;
        }
        __syncthreads();
        #pragma unroll
        for (int r = 0; r < 8; r++){
            float thr = s_run[arow[r]] + MARGIN;
            int rowg = rowbase + arow[r];
            #pragma unroll
            for (int c = 0; c < 8; c++){
                if (__int_as_float(acc[r][c]) < thr){
                    unsigned slot = atomicAdd(&g_cnt[rowg], 1u);
                    if (slot < MAX_CAND)
                        g_cand[rowg * MAX_CAND + slot] = nt * TILE_N + brow[c];
                }
                acc[r][c] = 0;
            }
        }
    }
}

// -------- exact fp32 rescue over candidates --------
__global__ void rescue_kernel(const float* __restrict__ z, const float* __restrict__ cb)
{
    const int row = blockIdx.x;
    const int lane = threadIdx.x;
    const unsigned cnt = g_cnt[row];
    const float zn = g_znorm[row];
    const float* zr = z + (size_t)row * D_DIM;

    float best = 3.4e38f;
    int bi = 0x7fffffff;

    if (cnt <= MAX_CAND){
        if (lane < (int)cnt){
            int cix = g_cand[row * MAX_CAND + lane];
            const float* cr = cb + (size_t)cix * D_DIM;
            float acc = 0.0f;
            #pragma unroll 8
            for (int k = 0; k < D_DIM; k++) acc = fmaf(zr[k], cr[k], acc);
            best = fmaf(-2.0f, acc, __fadd_rn(zn, g_cnorm[cix]));
            bi = cix;
        }
    } else {
        for (int cix = lane; cix < K_CODES; cix += 32){
            const float* cr = cb + (size_t)cix * D_DIM;
            float acc = 0.0f;
            #pragma unroll 8
            for (int k = 0; k < D_DIM; k++) acc = fmaf(zr[k], cr[k], acc);
            float d = fmaf(-2.0f, acc, __fadd_rn(zn, g_cnorm[cix]));
            if (d < best){ best = d; bi = cix; }
        }
    }
    #pragma unroll
    for (int o = 16; o > 0; o >>= 1){
        float ob = __shfl_down_sync(0xffffffffu, best, o);
        int   oi = __shfl_down_sync(0xffffffffu, bi, o);
        if (ob < best || (ob == best && oi < bi)){ best = ob; bi = oi; }
    }
    if (lane == 0){ g_idx[row] = bi; g_partial[row] = best; }
}

// -------- gather z_q + indices --------
__global__ void gather_kernel(const float* __restrict__ cb, float* __restrict__ out)
{
    int row = blockIdx.x, t = threadIdx.x;
    int id = g_idx[row];
    float4 v = ((const float4*)(cb + (size_t)id * D_DIM))[t];
    ((float4*)(out + (size_t)row * D_DIM))[t] = v;
    if (t == 0) out[(size_t)N_ROWS * D_DIM + row] = (float)id;
}

// -------- final loss --------
__global__ void loss_kernel(float* __restrict__ out){
    __shared__ double red[256];
    int t = threadIdx.x;
    double a = 0.0;
    for (int j = t; j < N_ROWS; j += 256) a += (double)g_partial[j];
    red[t] = a; __syncthreads();
    #pragma unroll
    for (int s = 128; s > 0; s >>= 1){
        if (t < s) red[t] += red[t + s];
        __syncthreads();
    }
    if (t == 0){
        float v = (float)(red[0] / ((double)N_ROWS * (double)D_DIM));
        out[(size_t)N_ROWS * D_DIM + N_ROWS] = __fadd_rn(v, 0.25f * v);
    }
}

extern "C" void kernel_launch(void* const* d_in, const int* in_sizes, int n_in,
                              void* d_out, int out_size)
{
    const float* z  = (const float*)d_in[0];   // [16384, 512]
    const float* cb = (const float*)d_in[1];   // [4096, 512]
    float* out = (float*)d_out;                // [z_q (N*D)] [idx (N)] [loss (1)]

    cudaFuncSetAttribute(vq_dp4a_kernel,
                         cudaFuncAttributeMaxDynamicSharedMemorySize, DYN_BYTES);

    prep_z_kernel<<<N_ROWS / 8, 256>>>(z);                 // launch 1
    quantc_kernel<<<K_CODES * 128 / 256, 256>>>(cb);       // launch 2
    cnorm_kernel<<<K_CODES / 8, 256>>>(cb);                // launch 3
    vq_dp4a_kernel<<<N_ROWS / TILE_M, 256, DYN_BYTES>>>(); // launch 4 (profiled)
    rescue_kernel<<<N_ROWS, 32>>>(z, cb);                  // launch 5
    gather_kernel<<<N_ROWS, 128>>>(cb, out);               // launch 6
    loss_kernel<<<1, 256>>>(out);                          // launch 7
}

// round 6
// speedup vs baseline: 7.1791x; 7.1791x over previous
#include <cuda_runtime.h>
#include <cstdint>

#define N_ROWS 16384
#define K_CODES 4096
#define D_DIM 512

#define TILE_M 128
#define TILE_N 128
#define NTILES 32

#define A_OFF 0
#define A_BYTES 65536             // 128 rows x 512 B
#define B_OFF 65536
#define B_STAGE 65536
#define CN_OFF (65536 * 3)
#define DYN_BYTES (CN_OFF + K_CODES * 4)   // 212992

#define MARGIN 1.0e-3f
#define MAX_CAND 64

#define SZQ (127.0f / 6.0f)                 // z quant scale
#define SCQ (127.0f * 4096.0f)              // codebook quant scale
// reconstruct: dist_approx = cn - 2*(SZ*SC)*idot, MS = -2*SZ*SC
#define MS  (-2.0f * (6.0f / 127.0f) / (127.0f * 4096.0f))

// -------- scratch (static device globals; no allocation) --------
__device__ int      g_zq[N_ROWS * 128];     // z int8 packed, 8 MB
__device__ int      g_cq[K_CODES * 128];    // codebook int8 packed, 2 MB
__device__ float    g_znorm[N_ROWS];
__device__ float    g_cnorm[K_CODES];
__device__ int      g_idx[N_ROWS];
__device__ float    g_partial[N_ROWS];
__device__ int      g_cand[N_ROWS * MAX_CAND];   // 4 MB
__device__ unsigned g_cnt[N_ROWS];

// -------- helpers --------
__device__ __forceinline__ unsigned smem_u32(const void* p){
    unsigned a;
    asm("{ .reg .u64 t; cvta.to.shared.u64 t, %1; cvt.u32.u64 %0, t; }" : "=r"(a) : "l"(p));
    return a;
}
__device__ __forceinline__ void cp16(unsigned s, const void* g){
    asm volatile("cp.async.cg.shared.global [%0], [%1], 16;" :: "r"(s), "l"(g) : "memory");
}
__device__ __forceinline__ void dp4(int& acc, unsigned a, unsigned b){
    asm("dp4a.s32.s32 %0, %1, %2, %0;" : "+r"(acc) : "r"(a), "r"(b));
}
__device__ __forceinline__ unsigned enc_f(float f){
    unsigned b = __float_as_uint(f);
    return (b & 0x80000000u) ? ~b : (b | 0x80000000u);
}
__device__ __forceinline__ float dec_f(unsigned e){
    return (e & 0x80000000u) ? __uint_as_float(e ^ 0x80000000u) : __uint_as_float(~e);
}
__device__ __forceinline__ int q8(float v, float s){
    float t = fminf(fmaxf(v * s, -127.0f), 127.0f);
    return __float2int_rn(t);
}
__device__ __forceinline__ int pack4(int a, int b, int c, int d){
    return (a & 255) | ((b & 255) << 8) | ((c & 255) << 16) | ((d & 255) << 24);
}

// -------- prep_z: fused fp64 row norm + int8 quant + cnt init (1 read of z) --
__global__ void prep_z_kernel(const float* __restrict__ z){
    int w = (blockIdx.x * blockDim.x + threadIdx.x) >> 5;
    int lane = threadIdx.x & 31;
    if (w >= N_ROWS) return;
    const float4* r4 = (const float4*)(z + (size_t)w * D_DIM);
    double acc = 0.0;
    #pragma unroll
    for (int j = 0; j < 4; j++){
        int widx = j * 32 + lane;
        float4 v = r4[widx];
        acc += (double)v.x * v.x + (double)v.y * v.y
             + (double)v.z * v.z + (double)v.w * v.w;
        g_zq[w * 128 + widx] = pack4(q8(v.x, SZQ), q8(v.y, SZQ), q8(v.z, SZQ), q8(v.w, SZQ));
    }
    #pragma unroll
    for (int o = 16; o > 0; o >>= 1) acc += __shfl_down_sync(0xffffffffu, acc, o);
    if (lane == 0){ g_znorm[w] = (float)acc; g_cnt[w] = 0u; }
}

// -------- prep_c: fused fp64 code norm + int8 quant (1 read of cb) --------
__global__ void prep_c_kernel(const float* __restrict__ cb){
    int w = (blockIdx.x * blockDim.x + threadIdx.x) >> 5;
    int lane = threadIdx.x & 31;
    if (w >= K_CODES) return;
    const float4* r4 = (const float4*)(cb + (size_t)w * D_DIM);
    double acc = 0.0;
    #pragma unroll
    for (int j = 0; j < 4; j++){
        int widx = j * 32 + lane;
        float4 v = r4[widx];
        acc += (double)v.x * v.x + (double)v.y * v.y
             + (double)v.z * v.z + (double)v.w * v.w;
        g_cq[w * 128 + widx] = pack4(q8(v.x, SCQ), q8(v.y, SCQ), q8(v.z, SCQ), q8(v.w, SCQ));
    }
    #pragma unroll
    for (int o = 16; o > 0; o >>= 1) acc += __shfl_down_sync(0xffffffffu, acc, o);
    if (lane == 0) g_cnorm[w] = (float)acc;
}

// -------- tile loaders (XOR-swizzled 16B chunks) --------
__device__ __forceinline__ void load_A(unsigned smA, int rowbase, int tid){
    const char* src = (const char*)g_zq;
    #pragma unroll
    for (int i = 0; i < 16; i++){
        int f = tid + i * 256;
        int r = f >> 5, c = f & 31;
        unsigned dst = smA + (unsigned)(r * 512 + ((c ^ ((r >> 2) & 7)) << 4));
        cp16(dst, src + (size_t)(rowbase + r) * 512 + (c << 4));
    }
}
__device__ __forceinline__ void load_B(unsigned smB, int nt, int tid){
    const char* src = (const char*)g_cq;
    #pragma unroll
    for (int i = 0; i < 16; i++){
        int f = tid + i * 256;
        int r = f >> 5, c = f & 31;
        unsigned dst = smB + (unsigned)(r * 512 + ((c ^ ((r >> 2) & 7)) << 4));
        cp16(dst, src + (size_t)(nt * TILE_N + r) * 512 + (c << 4));
    }
}

// -------- main int8 dp4a kernel: distances + candidate screening --------
extern __shared__ char sm_dyn[];
__global__ __launch_bounds__(256, 1)
void vq_dp4a_kernel()
{
    __shared__ unsigned s_tile[TILE_M];
    __shared__ float    s_run[TILE_M];

    const int tid = threadIdx.x;
    const int tx = tid & 15, ty = tid >> 4;
    const int rowbase = blockIdx.x * TILE_M;
    const unsigned smA = smem_u32(sm_dyn);
    float* cn_sm = (float*)(sm_dyn + CN_OFF);

    // prologue: A tile + B tile 0 (one cp.async group), cnorms, state init
    load_A(smA, rowbase, tid);
    load_B(smA + B_OFF, 0, tid);
    asm volatile("cp.async.commit_group;" ::: "memory");
    for (int i = tid; i < K_CODES; i += 256) cn_sm[i] = g_cnorm[i];
    if (tid < TILE_M){ s_tile[tid] = 0xFFFFFFFFu; s_run[tid] = 3.4e38f; }

    int acc[8][8];
    #pragma unroll
    for (int r = 0; r < 8; r++)
        #pragma unroll
        for (int c = 0; c < 8; c++) acc[r][c] = 0;

    int arow[8], brow[8];
    #pragma unroll
    for (int j = 0; j < 8; j++){
        arow[j] = (j < 4) ? (ty * 4 + j) : (64 + ty * 4 + j - 4);
        brow[j] = (j < 4) ? (tx * 4 + j) : (64 + tx * 4 + j - 4);
    }

    for (int nt = 0; nt < NTILES; nt++){
        if (nt + 1 < NTILES){
            load_B(smA + B_OFF + (unsigned)(((nt + 1) & 1) * B_STAGE), nt + 1, tid);
            asm volatile("cp.async.commit_group;" ::: "memory");
            asm volatile("cp.async.wait_group 1;" ::: "memory");
        } else {
            asm volatile("cp.async.wait_group 0;" ::: "memory");
        }
        __syncthreads();

        const char* Bb = sm_dyn + B_OFF + (nt & 1) * B_STAGE;

        #pragma unroll 1
        for (int kc = 0; kc < 32; kc++){
            uint4 a[8], b[8];
            #pragma unroll
            for (int j = 0; j < 8; j++){
                a[j] = *(const uint4*)(sm_dyn + arow[j] * 512 + ((kc ^ ((arow[j] >> 2) & 7)) << 4));
                b[j] = *(const uint4*)(Bb + brow[j] * 512 + ((kc ^ ((brow[j] >> 2) & 7)) << 4));
            }
            #pragma unroll
            for (int r = 0; r < 8; r++)
                #pragma unroll
                for (int c = 0; c < 8; c++){
                    dp4(acc[r][c], a[r].x, b[c].x);
                    dp4(acc[r][c], a[r].y, b[c].y);
                    dp4(acc[r][c], a[r].z, b[c].z);
                    dp4(acc[r][c], a[r].w, b[c].w);
                }
        }

        // ---- epilogue for tile nt ----
        float vmin[8];
        #pragma unroll
        for (int r = 0; r < 8; r++) vmin[r] = 3.4e38f;
        #pragma unroll
        for (int r = 0; r < 8; r++)
            #pragma unroll
            for (int c = 0; c < 8; c++){
                float fv = fmaf(MS, (float)acc[r][c], cn_sm[nt * TILE_N + brow[c]]);
                acc[r][c] = __float_as_int(fv);
                vmin[r] = fminf(vmin[r], fv);
            }
        #pragma unroll
        for (int r = 0; r < 8; r++)
            atomicMin(&s_tile[arow[r]], enc_f(vmin[r]));
        __syncthreads();
        if (tid < TILE_M){
            s_run[tid] = fminf(s_run[tid], dec_f(s_tile[tid]));
            s_tile[tid] = 0xFFFFFFFFu;
        }
        __syncthreads();
        #pragma unroll
        for (int r = 0; r < 8; r++){
            float thr = s_run[arow[r]] + MARGIN;
            int rowg = rowbase + arow[r];
            #pragma unroll
            for (int c = 0; c < 8; c++){
                if (__int_as_float(acc[r][c]) < thr){
                    unsigned slot = atomicAdd(&g_cnt[rowg], 1u);
                    if (slot < MAX_CAND)
                        g_cand[rowg * MAX_CAND + slot] = nt * TILE_N + brow[c];
                }
                acc[r][c] = 0;
            }
        }
    }
}

// -------- exact fp32 rescue (coalesced; warp per candidate) --------
__global__ __launch_bounds__(128, 8)
void rescue_kernel(const float* __restrict__ z, const float* __restrict__ cb)
{
    __shared__ __align__(16) float s_z[D_DIM];
    __shared__ float s_best[4];
    __shared__ int   s_bi[4];

    const int row  = blockIdx.x;
    const int tid  = threadIdx.x;
    const int warp = tid >> 5;
    const int lane = tid & 31;
    const unsigned cnt = g_cnt[row];
    const float zn = g_znorm[row];

    // stage z row in smem (coalesced float4)
    ((float4*)s_z)[tid] = ((const float4*)(z + (size_t)row * D_DIM))[tid];
    __syncthreads();

    const float4* z4 = (const float4*)s_z;
    float best = 3.4e38f;
    int bi = 0x7fffffff;

    if (cnt <= MAX_CAND){
        for (int k = warp; k < (int)cnt; k += 4){
            int cix = g_cand[row * MAX_CAND + k];
            const float4* c4 = (const float4*)(cb + (size_t)cix * D_DIM);
            float acc = 0.0f;
            #pragma unroll
            for (int i = 0; i < 4; i++){
                float4 cv = c4[i * 32 + lane];
                float4 zv = z4[i * 32 + lane];
                acc = fmaf(zv.x, cv.x, acc);
                acc = fmaf(zv.y, cv.y, acc);
                acc = fmaf(zv.z, cv.z, acc);
                acc = fmaf(zv.w, cv.w, acc);
            }
            #pragma unroll
            for (int o = 16; o > 0; o >>= 1)
                acc += __shfl_down_sync(0xffffffffu, acc, o);
            if (lane == 0){
                float d = fmaf(-2.0f, acc, __fadd_rn(zn, g_cnorm[cix]));
                if (d < best || (d == best && cix < bi)){ best = d; bi = cix; }
            }
        }
    } else {
        // overflow fallback (should be ~never taken): coalesced full scan
        for (int cix = warp; cix < K_CODES; cix += 4){
            const float4* c4 = (const float4*)(cb + (size_t)cix * D_DIM);
            float acc = 0.0f;
            #pragma unroll
            for (int i = 0; i < 4; i++){
                float4 cv = c4[i * 32 + lane];
                float4 zv = z4[i * 32 + lane];
                acc = fmaf(zv.x, cv.x, acc);
                acc = fmaf(zv.y, cv.y, acc);
                acc = fmaf(zv.z, cv.z, acc);
                acc = fmaf(zv.w, cv.w, acc);
            }
            #pragma unroll
            for (int o = 16; o > 0; o >>= 1)
                acc += __shfl_down_sync(0xffffffffu, acc, o);
            if (lane == 0){
                float d = fmaf(-2.0f, acc, __fadd_rn(zn, g_cnorm[cix]));
                if (d < best || (d == best && cix < bi)){ best = d; bi = cix; }
            }
        }
    }

    if (lane == 0){ s_best[warp] = best; s_bi[warp] = bi; }
    __syncthreads();
    if (tid == 0){
        float bv = s_best[0]; int bix = s_bi[0];
        #pragma unroll
        for (int w = 1; w < 4; w++){
            float vv = s_best[w]; int ii = s_bi[w];
            if (vv < bv || (vv == bv && ii < bix)){ bv = vv; bix = ii; }
        }
        g_idx[row] = bix;
        g_partial[row] = bv;
    }
}

// -------- gather z_q + indices --------
__global__ void gather_kernel(const float* __restrict__ cb, float* __restrict__ out)
{
    int row = blockIdx.x, t = threadIdx.x;
    int id = g_idx[row];
    float4 v = ((const float4*)(cb + (size_t)id * D_DIM))[t];
    ((float4*)(out + (size_t)row * D_DIM))[t] = v;
    if (t == 0) out[(size_t)N_ROWS * D_DIM + row] = (float)id;
}

// -------- final loss --------
__global__ void loss_kernel(float* __restrict__ out){
    __shared__ double red[256];
    int t = threadIdx.x;
    double a = 0.0;
    for (int j = t; j < N_ROWS; j += 256) a += (double)g_partial[j];
    red[t] = a; __syncthreads();
    #pragma unroll
    for (int s = 128; s > 0; s >>= 1){
        if (t < s) red[t] += red[t + s];
        __syncthreads();
    }
    if (t == 0){
        float v = (float)(red[0] / ((double)N_ROWS * (double)D_DIM));
        out[(size_t)N_ROWS * D_DIM + N_ROWS] = __fadd_rn(v, 0.25f * v);
    }
}

extern "C" void kernel_launch(void* const* d_in, const int* in_sizes, int n_in,
                              void* d_out, int out_size)
{
    const float* z  = (const float*)d_in[0];   // [16384, 512]
    const float* cb = (const float*)d_in[1];   // [4096, 512]
    float* out = (float*)d_out;                // [z_q (N*D)] [idx (N)] [loss (1)]

    cudaFuncSetAttribute(vq_dp4a_kernel,
                         cudaFuncAttributeMaxDynamicSharedMemorySize, DYN_BYTES);

    prep_z_kernel<<<N_ROWS / 8, 256>>>(z);                 // norms + quant, 1 read
    prep_c_kernel<<<K_CODES / 8, 256>>>(cb);
    vq_dp4a_kernel<<<N_ROWS / TILE_M, 256, DYN_BYTES>>>();
    rescue_kernel<<<N_ROWS, 128>>>(z, cb);
    gather_kernel<<<N_ROWS, 128>>>(cb, out);
    loss_kernel<<<1, 256>>>(out);
}